// round 1
// baseline (speedup 1.0000x reference)
#include <cuda_runtime.h>
#include <math.h>

#define BATCH 4
#define SEQ   2048
#define DIM   1024
#define HDIM  64
#define NCHUNK 16
#define CHUNK  128          // SEQ / NCHUNK
#define MROWS  (BATCH * SEQ)   // 8192

// ---------------- scratch (static device globals; no allocation) ----------------
__device__ float g_ret  [(size_t)MROWS * DIM];
__device__ float g_inp  [(size_t)MROWS * DIM];
__device__ float g_gate [(size_t)MROWS * DIM];
__device__ float g_u    [(size_t)MROWS * DIM];
__device__ float g_p    [(size_t)MROWS * DIM];
__device__ float g_state[(size_t)MROWS * DIM];
__device__ float g_E   [BATCH * NCHUNK * DIM];
__device__ float g_cin [BATCH * NCHUNK * DIM];
__device__ unsigned int g_bar;

// ---------------- retention scan ----------------
// pass1: chunk-local scan from zero, store chunk-end value
__global__ void scan_pass1(const float* __restrict__ K, const float* __restrict__ V,
                           const float* __restrict__ decay)
{
    int d = blockIdx.x * 256 + threadIdx.x;
    int c = blockIdx.y;
    int b = blockIdx.z;
    float dec = decay[d >> 6];
    size_t base = ((size_t)b * SEQ + (size_t)c * CHUNK) * DIM + d;
    const float* kp = K + base;
    const float* vp = V + base;
    float r = 0.f;
#pragma unroll 8
    for (int i = 0; i < CHUNK; ++i) {
        r = dec * r + kp[(size_t)i * DIM] * vp[(size_t)i * DIM];
    }
    g_E[((size_t)b * NCHUNK + c) * DIM + d] = r;
}

// pass2: exclusive prefix over chunk carries
__global__ void scan_pass2(const float* __restrict__ decay)
{
    int d = blockIdx.x * 256 + threadIdx.x;
    int b = blockIdx.y;
    float dec = decay[d >> 6];
    float decC = 1.f;
#pragma unroll
    for (int i = 0; i < CHUNK; ++i) decC *= dec;
    float carry = 0.f;
#pragma unroll
    for (int c = 0; c < NCHUNK; ++c) {
        size_t idx = ((size_t)b * NCHUNK + c) * DIM + d;
        g_cin[idx] = carry;
        carry = carry * decC + g_E[idx];
    }
}

// pass3: replay chunk with true carry, emit retained = q * r
__global__ void scan_pass3(const float* __restrict__ Q, const float* __restrict__ K,
                           const float* __restrict__ V, const float* __restrict__ decay)
{
    int d = blockIdx.x * 256 + threadIdx.x;
    int c = blockIdx.y;
    int b = blockIdx.z;
    float dec = decay[d >> 6];
    size_t base = ((size_t)b * SEQ + (size_t)c * CHUNK) * DIM + d;
    const float* qp = Q + base;
    const float* kp = K + base;
    const float* vp = V + base;
    float* rp = g_ret + base;
    float r = g_cin[((size_t)b * NCHUNK + c) * DIM + d];
#pragma unroll 8
    for (int i = 0; i < CHUNK; ++i) {
        r = dec * r + kp[(size_t)i * DIM] * vp[(size_t)i * DIM];
        rp[(size_t)i * DIM] = qp[(size_t)i * DIM] * r;
    }
}

// ---------------- SGEMM: C[m,n] = sum_k A[m*K+k] * B[n*K+k] (+epilogue) ----------------
// mode 0: C = acc + bias
// mode 1: gate: g = sigmoid(acc+bias); C = g; auxOut = (1-g) * auxIn
// mode 2: C += acc
// mode 3: C = acc
__global__ __launch_bounds__(256, 2)
void sgemm_nt(int M, int N, int Kd,
              const float* __restrict__ Am, const float* __restrict__ Bmat,
              const float* __restrict__ bias, float* __restrict__ C,
              const float* __restrict__ auxIn, float* __restrict__ auxOut, int mode)
{
    const int BM = 128, BN = 128, BK = 8, TM = 8, TN = 8;
    __shared__ float As[2][BK][BM];
    __shared__ float Bs[2][BK][BN];

    const int tid = threadIdx.x;
    const int mTile = blockIdx.y * BM;
    const int nTile = blockIdx.x * BN;
    const int lr = tid >> 1;
    const int lc = (tid & 1) * 4;
    const float* Ap = Am   + (size_t)(mTile + lr) * Kd + lc;
    const float* Bp = Bmat + (size_t)(nTile + lr) * Kd + lc;
    const int tr = (tid >> 4) * TM;
    const int tc = (tid & 15) * TN;

    float acc[TM][TN];
#pragma unroll
    for (int i = 0; i < TM; ++i)
#pragma unroll
        for (int j = 0; j < TN; ++j) acc[i][j] = 0.f;

    float4 a4 = *(const float4*)Ap;
    float4 b4 = *(const float4*)Bp;
    As[0][lc + 0][lr] = a4.x; As[0][lc + 1][lr] = a4.y;
    As[0][lc + 2][lr] = a4.z; As[0][lc + 3][lr] = a4.w;
    Bs[0][lc + 0][lr] = b4.x; Bs[0][lc + 1][lr] = b4.y;
    Bs[0][lc + 2][lr] = b4.z; Bs[0][lc + 3][lr] = b4.w;
    __syncthreads();

    int buf = 0;
    for (int kt = BK; kt <= Kd; kt += BK) {
        float4 na, nb;
        const bool more = (kt < Kd);
        if (more) {
            na = *(const float4*)(Ap + kt);
            nb = *(const float4*)(Bp + kt);
        }
#pragma unroll
        for (int kk = 0; kk < BK; ++kk) {
            float ra[TM], rb[TN];
            *(float4*)(ra)     = *(const float4*)&As[buf][kk][tr];
            *(float4*)(ra + 4) = *(const float4*)&As[buf][kk][tr + 4];
            *(float4*)(rb)     = *(const float4*)&Bs[buf][kk][tc];
            *(float4*)(rb + 4) = *(const float4*)&Bs[buf][kk][tc + 4];
#pragma unroll
            for (int i = 0; i < TM; ++i)
#pragma unroll
                for (int j = 0; j < TN; ++j)
                    acc[i][j] = fmaf(ra[i], rb[j], acc[i][j]);
        }
        if (more) {
            int nbuf = buf ^ 1;
            As[nbuf][lc + 0][lr] = na.x; As[nbuf][lc + 1][lr] = na.y;
            As[nbuf][lc + 2][lr] = na.z; As[nbuf][lc + 3][lr] = na.w;
            Bs[nbuf][lc + 0][lr] = nb.x; Bs[nbuf][lc + 1][lr] = nb.y;
            Bs[nbuf][lc + 2][lr] = nb.z; Bs[nbuf][lc + 3][lr] = nb.w;
            __syncthreads();
            buf = nbuf;
        }
    }

    float bv[TN];
    if (mode == 0 || mode == 1) {
#pragma unroll
        for (int j = 0; j < TN; ++j) bv[j] = bias[nTile + tc + j];
    }

#pragma unroll
    for (int i = 0; i < TM; ++i) {
        size_t row = (size_t)(mTile + tr + i);
        float* cp = C + row * N + nTile + tc;
        if (mode == 0) {
#pragma unroll
            for (int j = 0; j < TN; j += 4) {
                float4 v = make_float4(acc[i][j] + bv[j], acc[i][j + 1] + bv[j + 1],
                                       acc[i][j + 2] + bv[j + 2], acc[i][j + 3] + bv[j + 3]);
                *(float4*)(cp + j) = v;
            }
        } else if (mode == 3) {
#pragma unroll
            for (int j = 0; j < TN; j += 4) {
                float4 v = make_float4(acc[i][j], acc[i][j + 1], acc[i][j + 2], acc[i][j + 3]);
                *(float4*)(cp + j) = v;
            }
        } else if (mode == 2) {
#pragma unroll
            for (int j = 0; j < TN; j += 4) {
                float4 prev = *(const float4*)(cp + j);
                prev.x += acc[i][j];     prev.y += acc[i][j + 1];
                prev.z += acc[i][j + 2]; prev.w += acc[i][j + 3];
                *(float4*)(cp + j) = prev;
            }
        } else { // gate
            const float* ip = auxIn + row * N + nTile + tc;
            float* up = auxOut + row * N + nTile + tc;
#pragma unroll
            for (int j = 0; j < TN; ++j) {
                float g = 1.f / (1.f + expf(-(acc[i][j] + bv[j])));
                cp[j] = g;
                up[j] = (1.f - g) * ip[j];
            }
        }
    }
}

// ---------------- persistent state recurrence ----------------
// state_t = tanh( (gate_t (*) state_{t-1}) @ A^T + P_t ), 128 co-resident CTAs,
// 8 output columns per CTA, A slice resident in SMEM, global-atomic barrier per step.
#define REC_CTAS 128
#define REC_COLS 8
#define REC_SMEM ((REC_COLS * DIM + BATCH * DIM + 8 * 16) * 4)

__global__ __launch_bounds__(256, 1)
void recurrence_kernel(const float* __restrict__ gate, const float* __restrict__ P,
                       const float* __restrict__ Amat, float* __restrict__ state)
{
    extern __shared__ float sh[];
    float* Asub = sh;                        // [REC_COLS][DIM]
    float* xs   = sh + REC_COLS * DIM;       // [BATCH][DIM]
    float* red  = xs + BATCH * DIM;          // [8 warps][16]

    const int tid = threadIdx.x;
    const int col0 = blockIdx.x * REC_COLS;

    // load A slice (once)
    for (int i = tid; i < REC_COLS * DIM / 4; i += 256) {
        int c = i >> 8, k4 = i & 255;
        ((float4*)(Asub + c * DIM))[k4] =
            ((const float4*)(Amat + (size_t)(col0 + c) * DIM))[k4];
    }

    const int warp = tid >> 5, lane = tid & 31;
    const int cg = warp & 1;      // column group (4 cols)
    const int ks = warp >> 1;     // k split (256 floats each)

    for (int t = 0; t < SEQ; ++t) {
        // ---- stage x = gate_t * state_{t-1} into SMEM ----
        if (t == 0) {
            for (int i = tid; i < BATCH * DIM / 4; i += 256)
                ((float4*)xs)[i] = make_float4(0.f, 0.f, 0.f, 0.f);
        } else {
            for (int i = tid; i < BATCH * DIM / 4; i += 256) {
                int bb = i >> 8, k4 = i & 255;
                float4 g4 = ((const float4*)(gate + ((size_t)bb * SEQ + t) * DIM))[k4];
                float4 s4 = ((const float4*)(state + ((size_t)bb * SEQ + t - 1) * DIM))[k4];
                ((float4*)(xs + bb * DIM))[k4] =
                    make_float4(g4.x * s4.x, g4.y * s4.y, g4.z * s4.z, g4.w * s4.w);
            }
        }
        __syncthreads();

        // ---- partial dots: 4 batches x 4 cols over 256-float k slice ----
        float acc[4][4];
#pragma unroll
        for (int bb = 0; bb < 4; ++bb)
#pragma unroll
            for (int c = 0; c < 4; ++c) acc[bb][c] = 0.f;

#pragma unroll
        for (int i = 0; i < 2; ++i) {
            int k4 = ks * 64 + i * 32 + lane;
            float4 x4[4];
#pragma unroll
            for (int bb = 0; bb < 4; ++bb)
                x4[bb] = ((const float4*)(xs + bb * DIM))[k4];
#pragma unroll
            for (int c = 0; c < 4; ++c) {
                float4 a4 = ((const float4*)(Asub + (cg * 4 + c) * DIM))[k4];
#pragma unroll
                for (int bb = 0; bb < 4; ++bb) {
                    acc[bb][c] += x4[bb].x * a4.x + x4[bb].y * a4.y +
                                  x4[bb].z * a4.z + x4[bb].w * a4.w;
                }
            }
        }
        // intra-warp reduce
#pragma unroll
        for (int bb = 0; bb < 4; ++bb)
#pragma unroll
            for (int c = 0; c < 4; ++c) {
                float v = acc[bb][c];
#pragma unroll
                for (int off = 16; off; off >>= 1)
                    v += __shfl_xor_sync(0xffffffffu, v, off);
                acc[bb][c] = v;
            }
        if (lane == 0) {
#pragma unroll
            for (int bb = 0; bb < 4; ++bb)
#pragma unroll
                for (int c = 0; c < 4; ++c)
                    red[warp * 16 + bb * 4 + c] = acc[bb][c];
        }
        __syncthreads();

        // ---- finish: cross-warp sum, tanh, write state ----
        if (tid < 32) {
            int cg2 = tid >> 4, bb = (tid >> 2) & 3, c = tid & 3;
            float s = 0.f;
#pragma unroll
            for (int k = 0; k < 4; ++k)
                s += red[(k * 2 + cg2) * 16 + bb * 4 + c];
            size_t idx = ((size_t)bb * SEQ + t) * DIM + col0 + cg2 * 4 + c;
            state[idx] = tanhf(s + P[idx]);
            __threadfence();
        }
        __syncthreads();

        // ---- grid barrier ----
        if (tid == 0) {
            atomicAdd(&g_bar, 1u);
            unsigned tgt = (unsigned)(t + 1) * (unsigned)REC_CTAS;
            while (*(volatile unsigned*)&g_bar < tgt) { }
            __threadfence();
        }
        __syncthreads();
    }
}

__global__ void reset_bar() { g_bar = 0u; }

// ---------------- launch ----------------
extern "C" void kernel_launch(void* const* d_in, const int* in_sizes, int n_in,
                              void* d_out, int out_size)
{
    const float* q     = (const float*)d_in[0];
    const float* k     = (const float*)d_in[1];
    const float* v     = (const float*)d_in[2];
    const float* Wi    = (const float*)d_in[3];
    const float* bi    = (const float*)d_in[4];
    const float* Wg    = (const float*)d_in[5];
    const float* bg    = (const float*)d_in[6];
    const float* A     = (const float*)d_in[7];
    const float* Bm    = (const float*)d_in[8];
    const float* Wo    = (const float*)d_in[9];
    const float* bo    = (const float*)d_in[10];
    const float* decay = (const float*)d_in[11];

    float *ret, *inp, *gate, *u, *p, *state;
    cudaGetSymbolAddress((void**)&ret,   g_ret);
    cudaGetSymbolAddress((void**)&inp,   g_inp);
    cudaGetSymbolAddress((void**)&gate,  g_gate);
    cudaGetSymbolAddress((void**)&u,     g_u);
    cudaGetSymbolAddress((void**)&p,     g_p);
    cudaGetSymbolAddress((void**)&state, g_state);

    cudaFuncSetAttribute(recurrence_kernel,
                         cudaFuncAttributeMaxDynamicSharedMemorySize, REC_SMEM);

    dim3 sg(DIM / 256, NCHUNK, BATCH);
    scan_pass1<<<sg, 256>>>(k, v, decay);
    scan_pass2<<<dim3(DIM / 256, BATCH), 256>>>(decay);
    scan_pass3<<<sg, 256>>>(q, k, v, decay);

    dim3 gg(DIM / 128, MROWS / 128);
    // inp = ret @ Wi^T + bi
    sgemm_nt<<<gg, 256>>>(MROWS, DIM, DIM, ret, Wi, bi, inp, nullptr, nullptr, 0);
    // gate = sigmoid(inp @ Wg^T + bg); u = (1-gate) * inp
    sgemm_nt<<<gg, 256>>>(MROWS, DIM, DIM, inp, Wg, bg, gate, inp, u, 1);
    // p = u @ A^T
    sgemm_nt<<<gg, 256>>>(MROWS, DIM, DIM, u, A, nullptr, p, nullptr, nullptr, 3);
    // p += inp @ Bm^T
    sgemm_nt<<<gg, 256>>>(MROWS, DIM, DIM, inp, Bm, nullptr, p, nullptr, nullptr, 2);

    reset_bar<<<1, 1>>>();
    recurrence_kernel<<<REC_CTAS, 256, REC_SMEM>>>(gate, p, A, state);

    // out = state @ Wo^T + bo
    sgemm_nt<<<gg, 256>>>(MROWS, DIM, DIM, state, Wo, bo, (float*)d_out,
                          nullptr, nullptr, 0);
}

// round 2
// speedup vs baseline: 1.2730x; 1.2730x over previous
#include <cuda_runtime.h>
#include <math.h>

#define BATCH 4
#define SEQ   2048
#define DIM   1024
#define HDIM  64
#define NCHUNK 16
#define CHUNK  128          // SEQ / NCHUNK
#define MROWS  (BATCH * SEQ)   // 8192

// ---------------- scratch (static device globals; no allocation) ----------------
__device__ float g_ret  [(size_t)MROWS * DIM];
__device__ float g_inp  [(size_t)MROWS * DIM];
__device__ float g_gate [(size_t)MROWS * DIM];
__device__ float g_u    [(size_t)MROWS * DIM];
__device__ float g_p    [(size_t)MROWS * DIM];
__device__ float g_state[(size_t)MROWS * DIM];
__device__ float g_E   [BATCH * NCHUNK * DIM];
__device__ float g_cin [BATCH * NCHUNK * DIM];

#define REC_CTAS 128
#define REC_COLS 8
#define FLAG_STRIDE 8                       // 32B spacing -> distinct L2 sectors
__device__ unsigned int g_flags[REC_CTAS * FLAG_STRIDE];

// ---------------- retention scan ----------------
__global__ void scan_pass1(const float* __restrict__ K, const float* __restrict__ V,
                           const float* __restrict__ decay)
{
    int d = blockIdx.x * 256 + threadIdx.x;
    int c = blockIdx.y;
    int b = blockIdx.z;
    float dec = decay[d >> 6];
    size_t base = ((size_t)b * SEQ + (size_t)c * CHUNK) * DIM + d;
    const float* kp = K + base;
    const float* vp = V + base;
    float r = 0.f;
#pragma unroll 8
    for (int i = 0; i < CHUNK; ++i) {
        r = dec * r + kp[(size_t)i * DIM] * vp[(size_t)i * DIM];
    }
    g_E[((size_t)b * NCHUNK + c) * DIM + d] = r;
}

__global__ void scan_pass2(const float* __restrict__ decay)
{
    int d = blockIdx.x * 256 + threadIdx.x;
    int b = blockIdx.y;
    float dec = decay[d >> 6];
    float decC = 1.f;
#pragma unroll
    for (int i = 0; i < CHUNK; ++i) decC *= dec;
    float carry = 0.f;
#pragma unroll
    for (int c = 0; c < NCHUNK; ++c) {
        size_t idx = ((size_t)b * NCHUNK + c) * DIM + d;
        g_cin[idx] = carry;
        carry = carry * decC + g_E[idx];
    }
}

__global__ void scan_pass3(const float* __restrict__ Q, const float* __restrict__ K,
                           const float* __restrict__ V, const float* __restrict__ decay)
{
    int d = blockIdx.x * 256 + threadIdx.x;
    int c = blockIdx.y;
    int b = blockIdx.z;
    float dec = decay[d >> 6];
    size_t base = ((size_t)b * SEQ + (size_t)c * CHUNK) * DIM + d;
    const float* qp = Q + base;
    const float* kp = K + base;
    const float* vp = V + base;
    float* rp = g_ret + base;
    float r = g_cin[((size_t)b * NCHUNK + c) * DIM + d];
#pragma unroll 8
    for (int i = 0; i < CHUNK; ++i) {
        r = dec * r + kp[(size_t)i * DIM] * vp[(size_t)i * DIM];
        rp[(size_t)i * DIM] = qp[(size_t)i * DIM] * r;
    }
}

// ---------------- SGEMM: C[m,n] = sum_k A[m*K+k] * B[n*K+k] (+epilogue) ----------------
// mode 0: C = acc + bias
// mode 1: gate: g = sigmoid(acc+bias); C = g; auxOut = (1-g) * auxIn
// mode 2: C += acc
// mode 3: C = acc
__global__ __launch_bounds__(256, 2)
void sgemm_nt(int M, int N, int Kd,
              const float* __restrict__ Am, const float* __restrict__ Bmat,
              const float* __restrict__ bias, float* __restrict__ C,
              const float* __restrict__ auxIn, float* __restrict__ auxOut, int mode)
{
    const int BM = 128, BN = 128, BK = 8, TM = 8, TN = 8;
    __shared__ float As[2][BK][BM];
    __shared__ float Bs[2][BK][BN];

    const int tid = threadIdx.x;
    const int mTile = blockIdx.y * BM;
    const int nTile = blockIdx.x * BN;
    const int lr = tid >> 1;
    const int lc = (tid & 1) * 4;
    const float* Ap = Am   + (size_t)(mTile + lr) * Kd + lc;
    const float* Bp = Bmat + (size_t)(nTile + lr) * Kd + lc;
    const int tr = (tid >> 4) * TM;
    const int tc = (tid & 15) * TN;

    float acc[TM][TN];
#pragma unroll
    for (int i = 0; i < TM; ++i)
#pragma unroll
        for (int j = 0; j < TN; ++j) acc[i][j] = 0.f;

    float4 a4 = *(const float4*)Ap;
    float4 b4 = *(const float4*)Bp;
    As[0][lc + 0][lr] = a4.x; As[0][lc + 1][lr] = a4.y;
    As[0][lc + 2][lr] = a4.z; As[0][lc + 3][lr] = a4.w;
    Bs[0][lc + 0][lr] = b4.x; Bs[0][lc + 1][lr] = b4.y;
    Bs[0][lc + 2][lr] = b4.z; Bs[0][lc + 3][lr] = b4.w;
    __syncthreads();

    int buf = 0;
    for (int kt = BK; kt <= Kd; kt += BK) {
        float4 na, nb;
        const bool more = (kt < Kd);
        if (more) {
            na = *(const float4*)(Ap + kt);
            nb = *(const float4*)(Bp + kt);
        }
#pragma unroll
        for (int kk = 0; kk < BK; ++kk) {
            float ra[TM], rb[TN];
            *(float4*)(ra)     = *(const float4*)&As[buf][kk][tr];
            *(float4*)(ra + 4) = *(const float4*)&As[buf][kk][tr + 4];
            *(float4*)(rb)     = *(const float4*)&Bs[buf][kk][tc];
            *(float4*)(rb + 4) = *(const float4*)&Bs[buf][kk][tc + 4];
#pragma unroll
            for (int i = 0; i < TM; ++i)
#pragma unroll
                for (int j = 0; j < TN; ++j)
                    acc[i][j] = fmaf(ra[i], rb[j], acc[i][j]);
        }
        if (more) {
            int nbuf = buf ^ 1;
            As[nbuf][lc + 0][lr] = na.x; As[nbuf][lc + 1][lr] = na.y;
            As[nbuf][lc + 2][lr] = na.z; As[nbuf][lc + 3][lr] = na.w;
            Bs[nbuf][lc + 0][lr] = nb.x; Bs[nbuf][lc + 1][lr] = nb.y;
            Bs[nbuf][lc + 2][lr] = nb.z; Bs[nbuf][lc + 3][lr] = nb.w;
            __syncthreads();
            buf = nbuf;
        }
    }

    float bv[TN];
    if (mode == 0 || mode == 1) {
#pragma unroll
        for (int j = 0; j < TN; ++j) bv[j] = bias[nTile + tc + j];
    }

#pragma unroll
    for (int i = 0; i < TM; ++i) {
        size_t row = (size_t)(mTile + tr + i);
        float* cp = C + row * N + nTile + tc;
        if (mode == 0) {
#pragma unroll
            for (int j = 0; j < TN; j += 4) {
                float4 v = make_float4(acc[i][j] + bv[j], acc[i][j + 1] + bv[j + 1],
                                       acc[i][j + 2] + bv[j + 2], acc[i][j + 3] + bv[j + 3]);
                *(float4*)(cp + j) = v;
            }
        } else if (mode == 3) {
#pragma unroll
            for (int j = 0; j < TN; j += 4) {
                float4 v = make_float4(acc[i][j], acc[i][j + 1], acc[i][j + 2], acc[i][j + 3]);
                *(float4*)(cp + j) = v;
            }
        } else if (mode == 2) {
#pragma unroll
            for (int j = 0; j < TN; j += 4) {
                float4 prev = *(const float4*)(cp + j);
                prev.x += acc[i][j];     prev.y += acc[i][j + 1];
                prev.z += acc[i][j + 2]; prev.w += acc[i][j + 3];
                *(float4*)(cp + j) = prev;
            }
        } else { // gate
            const float* ip = auxIn + row * N + nTile + tc;
            float* up = auxOut + row * N + nTile + tc;
#pragma unroll
            for (int j = 0; j < TN; ++j) {
                float g = 1.f / (1.f + __expf(-(acc[i][j] + bv[j])));
                cp[j] = g;
                up[j] = (1.f - g) * ip[j];
            }
        }
    }
}

// ---------------- persistent state recurrence (v2: flag barrier, prefetch) ----------------
// state_t = tanh( (gate_t (*) state_{t-1}) @ A^T + P_t )
// 128 co-resident CTAs, 8 output columns each, A slice resident in SMEM.
// Sync: distributed per-CTA epoch flags (32B-strided), warp0 polls all 128.
#define REC_SMEM ((REC_COLS * DIM + BATCH * DIM + 8 * 16) * 4)

__global__ __launch_bounds__(256, 1)
void recurrence_kernel(const float* __restrict__ gate, const float* __restrict__ P,
                       const float* __restrict__ Amat, float* __restrict__ state)
{
    extern __shared__ float sh[];
    float* Asub = sh;                        // [REC_COLS][DIM]
    float* xs   = sh + REC_COLS * DIM;       // [BATCH][DIM]
    float* red  = xs + BATCH * DIM;          // [8 warps][16]

    const int tid = threadIdx.x;
    const int warp = tid >> 5, lane = tid & 31;
    const int col0 = blockIdx.x * REC_COLS;
    const int cg = warp & 1;      // column group (4 cols)
    const int ks = warp >> 1;     // k split (256 floats each)

    // load A slice (once)
    for (int i = tid; i < REC_COLS * DIM / 4; i += 256) {
        int c = i >> 8, k4 = i & 255;
        ((float4*)(Asub + c * DIM))[k4] =
            ((const float4*)(Amat + (size_t)(col0 + c) * DIM))[k4];
    }

    // finisher-thread (tid<32) output coordinates
    const int f_cg = tid >> 4, f_bb = (tid >> 2) & 3, f_c = tid & 3;
    const int f_col = col0 + f_cg * 4 + f_c;

    __syncthreads();

    for (int t = 0; t < SEQ; ++t) {
        // ---- (A) prefetch gate_t (regs) and P_t (finisher) — independent of barrier ----
        float4 gpre[4];
        int pbb[4], pk4[4];
#pragma unroll
        for (int j = 0; j < 4; ++j) {
            int idx = tid + j * 256;          // float4 index in [0,1024)
            pbb[j] = idx >> 8;
            pk4[j] = idx & 255;
            gpre[j] = ((const float4*)(gate + ((size_t)pbb[j] * SEQ + t) * DIM))[pk4[j]];
        }
        float pval = 0.f;
        if (tid < 32)
            pval = P[((size_t)f_bb * SEQ + t) * DIM + f_col];

        // ---- (B) wait: all CTAs have published state_{t-1} (flag >= t) ----
        if (t > 0 && warp == 0) {
            unsigned tgt = (unsigned)t;
            bool ok;
            do {
                bool good = true;
#pragma unroll
                for (int j = 0; j < 4; ++j) {
                    unsigned f = *(volatile const unsigned*)
                        &g_flags[(lane + 32 * j) * FLAG_STRIDE];
                    good = good && (f >= tgt);
                }
                ok = __all_sync(0xffffffffu, good);
            } while (!ok);
        }
        __syncthreads();

        // ---- (C) stage x = gate_t * state_{t-1} into SMEM ----
        if (t == 0) {
#pragma unroll
            for (int j = 0; j < 4; ++j)
                ((float4*)(xs + pbb[j] * DIM))[pk4[j]] = make_float4(0.f, 0.f, 0.f, 0.f);
        } else {
#pragma unroll
            for (int j = 0; j < 4; ++j) {
                float4 s4 = __ldcg(&((const float4*)(state + ((size_t)pbb[j] * SEQ + t - 1) * DIM))[pk4[j]]);
                float4 g4 = gpre[j];
                ((float4*)(xs + pbb[j] * DIM))[pk4[j]] =
                    make_float4(g4.x * s4.x, g4.y * s4.y, g4.z * s4.z, g4.w * s4.w);
            }
        }
        __syncthreads();

        // ---- (D) partial dots: 4 batches x 4 cols over 256-float k slice ----
        float acc[4][4];
#pragma unroll
        for (int bb = 0; bb < 4; ++bb)
#pragma unroll
            for (int c = 0; c < 4; ++c) acc[bb][c] = 0.f;

#pragma unroll
        for (int i = 0; i < 2; ++i) {
            int k4 = ks * 64 + i * 32 + lane;
            float4 x4[4];
#pragma unroll
            for (int bb = 0; bb < 4; ++bb)
                x4[bb] = ((const float4*)(xs + bb * DIM))[k4];
#pragma unroll
            for (int c = 0; c < 4; ++c) {
                float4 a4 = ((const float4*)(Asub + (cg * 4 + c) * DIM))[k4];
#pragma unroll
                for (int bb = 0; bb < 4; ++bb) {
                    acc[bb][c] += x4[bb].x * a4.x + x4[bb].y * a4.y +
                                  x4[bb].z * a4.z + x4[bb].w * a4.w;
                }
            }
        }
#pragma unroll
        for (int bb = 0; bb < 4; ++bb)
#pragma unroll
            for (int c = 0; c < 4; ++c) {
                float v = acc[bb][c];
#pragma unroll
                for (int off = 16; off; off >>= 1)
                    v += __shfl_xor_sync(0xffffffffu, v, off);
                acc[bb][c] = v;
            }
        if (lane == 0) {
#pragma unroll
            for (int bb = 0; bb < 4; ++bb)
#pragma unroll
                for (int c = 0; c < 4; ++c)
                    red[warp * 16 + bb * 4 + c] = acc[bb][c];
        }
        __syncthreads();

        // ---- (E) finish: cross-warp sum, tanh, publish state ----
        if (tid < 32) {
            float s = 0.f;
#pragma unroll
            for (int k = 0; k < 4; ++k)
                s += red[(k * 2 + f_cg) * 16 + f_bb * 4 + f_c];
            size_t idx = ((size_t)f_bb * SEQ + t) * DIM + f_col;
            __stcg(&state[idx], tanhf(s + pval));
            __threadfence();   // make this thread's store visible at gpu scope
        }
        __syncthreads();

        // ---- (F) arrive: publish epoch on own flag (distinct address) ----
        if (tid == 0)
            *(volatile unsigned*)&g_flags[blockIdx.x * FLAG_STRIDE] = (unsigned)(t + 1);
        __syncthreads();
    }
}

__global__ void reset_flags()
{
    int i = threadIdx.x;
    if (i < REC_CTAS * FLAG_STRIDE) g_flags[i] = 0u;
}

// ---------------- launch ----------------
extern "C" void kernel_launch(void* const* d_in, const int* in_sizes, int n_in,
                              void* d_out, int out_size)
{
    const float* q     = (const float*)d_in[0];
    const float* k     = (const float*)d_in[1];
    const float* v     = (const float*)d_in[2];
    const float* Wi    = (const float*)d_in[3];
    const float* bi    = (const float*)d_in[4];
    const float* Wg    = (const float*)d_in[5];
    const float* bg    = (const float*)d_in[6];
    const float* A     = (const float*)d_in[7];
    const float* Bm    = (const float*)d_in[8];
    const float* Wo    = (const float*)d_in[9];
    const float* bo    = (const float*)d_in[10];
    const float* decay = (const float*)d_in[11];

    float *ret, *inp, *gate, *u, *p, *state;
    cudaGetSymbolAddress((void**)&ret,   g_ret);
    cudaGetSymbolAddress((void**)&inp,   g_inp);
    cudaGetSymbolAddress((void**)&gate,  g_gate);
    cudaGetSymbolAddress((void**)&u,     g_u);
    cudaGetSymbolAddress((void**)&p,     g_p);
    cudaGetSymbolAddress((void**)&state, g_state);

    cudaFuncSetAttribute(recurrence_kernel,
                         cudaFuncAttributeMaxDynamicSharedMemorySize, REC_SMEM);

    dim3 sg(DIM / 256, NCHUNK, BATCH);
    scan_pass1<<<sg, 256>>>(k, v, decay);
    scan_pass2<<<dim3(DIM / 256, BATCH), 256>>>(decay);
    scan_pass3<<<sg, 256>>>(q, k, v, decay);

    dim3 gg(DIM / 128, MROWS / 128);
    // inp = ret @ Wi^T + bi
    sgemm_nt<<<gg, 256>>>(MROWS, DIM, DIM, ret, Wi, bi, inp, nullptr, nullptr, 0);
    // gate = sigmoid(inp @ Wg^T + bg); u = (1-gate) * inp
    sgemm_nt<<<gg, 256>>>(MROWS, DIM, DIM, inp, Wg, bg, gate, inp, u, 1);
    // p = u @ A^T
    sgemm_nt<<<gg, 256>>>(MROWS, DIM, DIM, u, A, nullptr, p, nullptr, nullptr, 3);
    // p += inp @ Bm^T
    sgemm_nt<<<gg, 256>>>(MROWS, DIM, DIM, inp, Bm, nullptr, p, nullptr, nullptr, 2);

    reset_flags<<<1, 1024>>>();
    recurrence_kernel<<<REC_CTAS, 256, REC_SMEM>>>(gate, p, A, state);

    // out = state @ Wo^T + bo
    sgemm_nt<<<gg, 256>>>(MROWS, DIM, DIM, state, Wo, bo, (float*)d_out,
                          nullptr, nullptr, 0);
}

// round 5
// speedup vs baseline: 1.4098x; 1.1075x over previous
#include <cuda_runtime.h>
#include <math.h>

#define BATCH 4
#define SEQ   2048
#define DIM   1024
#define HDIM  64
#define NCHUNK 16
#define CHUNK  128          // SEQ / NCHUNK
#define MROWS  (BATCH * SEQ)   // 8192

// ---------------- scratch (static device globals; no allocation) ----------------
__device__ float g_ret  [(size_t)MROWS * DIM];
__device__ float g_inp  [(size_t)MROWS * DIM];
__device__ float g_gate [(size_t)MROWS * DIM];
__device__ float g_u    [(size_t)MROWS * DIM];
__device__ float g_p    [(size_t)MROWS * DIM];
__device__ float g_state[(size_t)MROWS * DIM];
__device__ float g_y    [(size_t)MROWS * DIM];   // y_t = gate_{t+1} * state_t

#define REC_CTAS 128
#define REC_COLS 8
#define FLAG_STRIDE 8                       // 32B spacing -> distinct L2 sectors
__device__ unsigned int g_flags[REC_CTAS * FLAG_STRIDE];

__device__ float g_E   [BATCH * NCHUNK * DIM];
__device__ float g_cin [BATCH * NCHUNK * DIM];

// ---------------- retention scan ----------------
__global__ void scan_pass1(const float* __restrict__ K, const float* __restrict__ V,
                           const float* __restrict__ decay)
{
    int d = blockIdx.x * 256 + threadIdx.x;
    int c = blockIdx.y;
    int b = blockIdx.z;
    float dec = decay[d >> 6];
    size_t base = ((size_t)b * SEQ + (size_t)c * CHUNK) * DIM + d;
    const float* kp = K + base;
    const float* vp = V + base;
    float r = 0.f;
#pragma unroll 8
    for (int i = 0; i < CHUNK; ++i) {
        r = dec * r + kp[(size_t)i * DIM] * vp[(size_t)i * DIM];
    }
    g_E[((size_t)b * NCHUNK + c) * DIM + d] = r;
}

__global__ void scan_pass2(const float* __restrict__ decay)
{
    int d = blockIdx.x * 256 + threadIdx.x;
    int b = blockIdx.y;
    float dec = decay[d >> 6];
    float decC = 1.f;
#pragma unroll
    for (int i = 0; i < CHUNK; ++i) decC *= dec;
    float carry = 0.f;
#pragma unroll
    for (int c = 0; c < NCHUNK; ++c) {
        size_t idx = ((size_t)b * NCHUNK + c) * DIM + d;
        g_cin[idx] = carry;
        carry = carry * decC + g_E[idx];
    }
}

__global__ void scan_pass3(const float* __restrict__ Q, const float* __restrict__ K,
                           const float* __restrict__ V, const float* __restrict__ decay)
{
    int d = blockIdx.x * 256 + threadIdx.x;
    int c = blockIdx.y;
    int b = blockIdx.z;
    float dec = decay[d >> 6];
    size_t base = ((size_t)b * SEQ + (size_t)c * CHUNK) * DIM + d;
    const float* qp = Q + base;
    const float* kp = K + base;
    const float* vp = V + base;
    float* rp = g_ret + base;
    float r = g_cin[((size_t)b * NCHUNK + c) * DIM + d];
#pragma unroll 8
    for (int i = 0; i < CHUNK; ++i) {
        r = dec * r + kp[(size_t)i * DIM] * vp[(size_t)i * DIM];
        rp[(size_t)i * DIM] = qp[(size_t)i * DIM] * r;
    }
}

// ---------------- SGEMM: C[m,n] = sum_k A[m*K+k] * B[n*K+k] (+epilogue) ----------------
// mode 0: C = acc + bias
// mode 1: gate: g = sigmoid(acc+bias); C = g; auxOut = (1-g) * auxIn
// mode 2: C += acc
// mode 3: C = acc
__global__ __launch_bounds__(256, 2)
void sgemm_nt(int M, int N, int Kd,
              const float* __restrict__ Am, const float* __restrict__ Bmat,
              const float* __restrict__ bias, float* __restrict__ C,
              const float* __restrict__ auxIn, float* __restrict__ auxOut, int mode)
{
    const int BM = 128, BN = 128, BK = 8, TM = 8, TN = 8;
    __shared__ float As[2][BK][BM];
    __shared__ float Bs[2][BK][BN];

    const int tid = threadIdx.x;
    const int mTile = blockIdx.y * BM;
    const int nTile = blockIdx.x * BN;
    const int lr = tid >> 1;
    const int lc = (tid & 1) * 4;
    const float* Ap = Am   + (size_t)(mTile + lr) * Kd + lc;
    const float* Bp = Bmat + (size_t)(nTile + lr) * Kd + lc;
    const int tr = (tid >> 4) * TM;
    const int tc = (tid & 15) * TN;

    float acc[TM][TN];
#pragma unroll
    for (int i = 0; i < TM; ++i)
#pragma unroll
        for (int j = 0; j < TN; ++j) acc[i][j] = 0.f;

    float4 a4 = *(const float4*)Ap;
    float4 b4 = *(const float4*)Bp;
    As[0][lc + 0][lr] = a4.x; As[0][lc + 1][lr] = a4.y;
    As[0][lc + 2][lr] = a4.z; As[0][lc + 3][lr] = a4.w;
    Bs[0][lc + 0][lr] = b4.x; Bs[0][lc + 1][lr] = b4.y;
    Bs[0][lc + 2][lr] = b4.z; Bs[0][lc + 3][lr] = b4.w;
    __syncthreads();

    int buf = 0;
    for (int kt = BK; kt <= Kd; kt += BK) {
        float4 na, nb;
        const bool more = (kt < Kd);
        if (more) {
            na = *(const float4*)(Ap + kt);
            nb = *(const float4*)(Bp + kt);
        }
#pragma unroll
        for (int kk = 0; kk < BK; ++kk) {
            float ra[TM], rb[TN];
            *(float4*)(ra)     = *(const float4*)&As[buf][kk][tr];
            *(float4*)(ra + 4) = *(const float4*)&As[buf][kk][tr + 4];
            *(float4*)(rb)     = *(const float4*)&Bs[buf][kk][tc];
            *(float4*)(rb + 4) = *(const float4*)&Bs[buf][kk][tc + 4];
#pragma unroll
            for (int i = 0; i < TM; ++i)
#pragma unroll
                for (int j = 0; j < TN; ++j)
                    acc[i][j] = fmaf(ra[i], rb[j], acc[i][j]);
        }
        if (more) {
            int nbuf = buf ^ 1;
            As[nbuf][lc + 0][lr] = na.x; As[nbuf][lc + 1][lr] = na.y;
            As[nbuf][lc + 2][lr] = na.z; As[nbuf][lc + 3][lr] = na.w;
            Bs[nbuf][lc + 0][lr] = nb.x; Bs[nbuf][lc + 1][lr] = nb.y;
            Bs[nbuf][lc + 2][lr] = nb.z; Bs[nbuf][lc + 3][lr] = nb.w;
            __syncthreads();
            buf = nbuf;
        }
    }

    float bv[TN];
    if (mode == 0 || mode == 1) {
#pragma unroll
        for (int j = 0; j < TN; ++j) bv[j] = bias[nTile + tc + j];
    }

#pragma unroll
    for (int i = 0; i < TM; ++i) {
        size_t row = (size_t)(mTile + tr + i);
        float* cp = C + row * N + nTile + tc;
        if (mode == 0) {
#pragma unroll
            for (int j = 0; j < TN; j += 4) {
                float4 v = make_float4(acc[i][j] + bv[j], acc[i][j + 1] + bv[j + 1],
                                       acc[i][j + 2] + bv[j + 2], acc[i][j + 3] + bv[j + 3]);
                *(float4*)(cp + j) = v;
            }
        } else if (mode == 3) {
#pragma unroll
            for (int j = 0; j < TN; j += 4) {
                float4 v = make_float4(acc[i][j], acc[i][j + 1], acc[i][j + 2], acc[i][j + 3]);
                *(float4*)(cp + j) = v;
            }
        } else if (mode == 2) {
#pragma unroll
            for (int j = 0; j < TN; j += 4) {
                float4 prev = *(const float4*)(cp + j);
                prev.x += acc[i][j];     prev.y += acc[i][j + 1];
                prev.z += acc[i][j + 2]; prev.w += acc[i][j + 3];
                *(float4*)(cp + j) = prev;
            }
        } else { // gate
            const float* ip = auxIn + row * N + nTile + tc;
            float* up = auxOut + row * N + nTile + tc;
#pragma unroll
            for (int j = 0; j < TN; ++j) {
                float g = 1.f / (1.f + __expf(-(acc[i][j] + bv[j])));
                cp[j] = g;
                up[j] = (1.f - g) * ip[j];
            }
        }
    }
}

// ---------------- persistent state recurrence (v5: round-2 protocol + gate-fold) ----------------
// state_t = tanh( y_{t-1} @ A^T + P_t ),  y_t = gate_{t+1} (*) state_t  (producer-folded)
// 128 co-resident CTAs, 8 output columns each, A slice resident in SMEM.
// Sync: PROVEN round-2 protocol — per-CTA epoch flags (32B-strided), producer:
// stcg y/state -> threadfence -> syncthreads -> tid0 volatile flag store;
// consumer: warp0 volatile-polls all 128 flags, then ldcg y.
#define REC_SMEM ((REC_COLS * DIM + BATCH * DIM + 8 * 16) * 4)

__global__ __launch_bounds__(256, 1)
void recurrence_kernel(const float* __restrict__ gate, const float* __restrict__ P,
                       const float* __restrict__ Amat, float* __restrict__ state)
{
    extern __shared__ float sh[];
    float* Asub = sh;                        // [REC_COLS][DIM]
    float* xs   = sh + REC_COLS * DIM;       // [BATCH][DIM]  (holds y_{t-1})
    float* red  = xs + BATCH * DIM;          // [8 warps][16]

    const int tid = threadIdx.x;
    const int warp = tid >> 5, lane = tid & 31;
    const int col0 = blockIdx.x * REC_COLS;
    const int cg = warp & 1;      // column group (4 cols)
    const int ks = warp >> 1;     // k split (256 floats each)

    // load A slice (once)
    for (int i = tid; i < REC_COLS * DIM / 4; i += 256) {
        int c = i >> 8, k4 = i & 255;
        ((float4*)(Asub + c * DIM))[k4] =
            ((const float4*)(Amat + (size_t)(col0 + c) * DIM))[k4];
    }

    // finisher-thread (tid<32) output coordinates
    const int f_cg = tid >> 4, f_bb = (tid >> 2) & 3, f_c = tid & 3;
    const int f_col = col0 + f_cg * 4 + f_c;

    // staging coordinates (4 float4 per thread)
    int pbb[4], pk4[4];
#pragma unroll
    for (int j = 0; j < 4; ++j) {
        int idx = tid + j * 256;
        pbb[j] = idx >> 8;
        pk4[j] = idx & 255;
    }

    __syncthreads();

    for (int t = 0; t < SEQ; ++t) {
        // ---- (A) prefetch P_t and gate_{t+1} (finisher only; barrier-independent) ----
        float pval = 0.f, gval = 0.f;
        if (tid < 32) {
            pval = P[((size_t)f_bb * SEQ + t) * DIM + f_col];
            if (t + 1 < SEQ)
                gval = gate[((size_t)f_bb * SEQ + (t + 1)) * DIM + f_col];
        }

        // ---- (B) wait: all CTAs have published y_{t-1} (flag >= t) ----
        if (t > 0 && warp == 0) {
            unsigned tgt = (unsigned)t;
            bool ok;
            do {
                bool good = true;
#pragma unroll
                for (int j = 0; j < 4; ++j) {
                    unsigned f = *(volatile const unsigned*)
                        &g_flags[(lane + 32 * j) * FLAG_STRIDE];
                    good = good && (f >= tgt);
                }
                ok = __all_sync(0xffffffffu, good);
            } while (!ok);
        }
        __syncthreads();

        // ---- (C) stage y_{t-1} into SMEM (single stream; gate already folded) ----
        if (t == 0) {
#pragma unroll
            for (int j = 0; j < 4; ++j)
                ((float4*)(xs + pbb[j] * DIM))[pk4[j]] = make_float4(0.f, 0.f, 0.f, 0.f);
        } else {
#pragma unroll
            for (int j = 0; j < 4; ++j) {
                float4 y4 = __ldcg(&((const float4*)(g_y + ((size_t)pbb[j] * SEQ + t - 1) * DIM))[pk4[j]]);
                ((float4*)(xs + pbb[j] * DIM))[pk4[j]] = y4;
            }
        }
        __syncthreads();

        // ---- (D) partial dots: 4 batches x 4 cols over 256-float k slice ----
        float acc[4][4];
#pragma unroll
        for (int bb = 0; bb < 4; ++bb)
#pragma unroll
            for (int c = 0; c < 4; ++c) acc[bb][c] = 0.f;

#pragma unroll
        for (int i = 0; i < 2; ++i) {
            int k4 = ks * 64 + i * 32 + lane;
            float4 x4[4];
#pragma unroll
            for (int bb = 0; bb < 4; ++bb)
                x4[bb] = ((const float4*)(xs + bb * DIM))[k4];
#pragma unroll
            for (int c = 0; c < 4; ++c) {
                float4 a4 = ((const float4*)(Asub + (cg * 4 + c) * DIM))[k4];
#pragma unroll
                for (int bb = 0; bb < 4; ++bb) {
                    acc[bb][c] += x4[bb].x * a4.x + x4[bb].y * a4.y +
                                  x4[bb].z * a4.z + x4[bb].w * a4.w;
                }
            }
        }
#pragma unroll
        for (int bb = 0; bb < 4; ++bb)
#pragma unroll
            for (int c = 0; c < 4; ++c) {
                float v = acc[bb][c];
#pragma unroll
                for (int off = 16; off; off >>= 1)
                    v += __shfl_xor_sync(0xffffffffu, v, off);
                acc[bb][c] = v;
            }
        if (lane == 0) {
#pragma unroll
            for (int bb = 0; bb < 4; ++bb)
#pragma unroll
                for (int c = 0; c < 4; ++c)
                    red[warp * 16 + bb * 4 + c] = acc[bb][c];
        }
        __syncthreads();

        // ---- (E) finish: cross-warp sum, tanh, publish state and folded y ----
        if (tid < 32) {
            float s = 0.f;
#pragma unroll
            for (int k = 0; k < 4; ++k)
                s += red[(k * 2 + f_cg) * 16 + f_bb * 4 + f_c];
            float sv = tanhf(s + pval);
            size_t idx = ((size_t)f_bb * SEQ + t) * DIM + f_col;
            __stcg(&state[idx], sv);
            if (t + 1 < SEQ)
                __stcg(&g_y[idx], sv * gval);
            __threadfence();   // make this thread's stores visible at gpu scope
        }
        __syncthreads();

        // ---- (F) arrive: publish epoch on own flag (distinct address) ----
        if (tid == 0)
            *(volatile unsigned*)&g_flags[blockIdx.x * FLAG_STRIDE] = (unsigned)(t + 1);
        __syncthreads();
    }
}

__global__ void reset_flags()
{
    int i = threadIdx.x;
    if (i < REC_CTAS * FLAG_STRIDE) g_flags[i] = 0u;
}

// ---------------- launch ----------------
extern "C" void kernel_launch(void* const* d_in, const int* in_sizes, int n_in,
                              void* d_out, int out_size)
{
    const float* q     = (const float*)d_in[0];
    const float* k     = (const float*)d_in[1];
    const float* v     = (const float*)d_in[2];
    const float* Wi    = (const float*)d_in[3];
    const float* bi    = (const float*)d_in[4];
    const float* Wg    = (const float*)d_in[5];
    const float* bg    = (const float*)d_in[6];
    const float* A     = (const float*)d_in[7];
    const float* Bm    = (const float*)d_in[8];
    const float* Wo    = (const float*)d_in[9];
    const float* bo    = (const float*)d_in[10];
    const float* decay = (const float*)d_in[11];

    float *ret, *inp, *gate, *u, *p, *state;
    cudaGetSymbolAddress((void**)&ret,   g_ret);
    cudaGetSymbolAddress((void**)&inp,   g_inp);
    cudaGetSymbolAddress((void**)&gate,  g_gate);
    cudaGetSymbolAddress((void**)&u,     g_u);
    cudaGetSymbolAddress((void**)&p,     g_p);
    cudaGetSymbolAddress((void**)&state, g_state);

    cudaFuncSetAttribute(recurrence_kernel,
                         cudaFuncAttributeMaxDynamicSharedMemorySize, REC_SMEM);

    dim3 sg(DIM / 256, NCHUNK, BATCH);
    scan_pass1<<<sg, 256>>>(k, v, decay);
    scan_pass2<<<dim3(DIM / 256, BATCH), 256>>>(decay);
    scan_pass3<<<sg, 256>>>(q, k, v, decay);

    dim3 gg(DIM / 128, MROWS / 128);
    // inp = ret @ Wi^T + bi
    sgemm_nt<<<gg, 256>>>(MROWS, DIM, DIM, ret, Wi, bi, inp, nullptr, nullptr, 0);
    // gate = sigmoid(inp @ Wg^T + bg); u = (1-gate) * inp
    sgemm_nt<<<gg, 256>>>(MROWS, DIM, DIM, inp, Wg, bg, gate, inp, u, 1);
    // p = u @ A^T
    sgemm_nt<<<gg, 256>>>(MROWS, DIM, DIM, u, A, nullptr, p, nullptr, nullptr, 3);
    // p += inp @ Bm^T
    sgemm_nt<<<gg, 256>>>(MROWS, DIM, DIM, inp, Bm, nullptr, p, nullptr, nullptr, 2);

    reset_flags<<<1, 1024>>>();
    recurrence_kernel<<<REC_CTAS, 256, REC_SMEM>>>(gate, p, A, state);

    // out = state @ Wo^T + bo
    sgemm_nt<<<gg, 256>>>(MROWS, DIM, DIM, state, Wo, bo, (float*)d_out,
                          nullptr, nullptr, 0);
}